// round 8
// baseline (speedup 1.0000x reference)
#include <cuda_runtime.h>
#include <cuda_bf16.h>
#include <math.h>
#include <stdint.h>

#define B_DIM 2048
#define D_DIM 512
#define C_DIM 32000
#define SCALE_F 32.0f
#define MARGIN_F 16.0f

// ---------------- scratch (device globals; no allocation allowed) ----------
__device__ float g_invnx[B_DIM];
__device__ float g_invnw[C_DIM];
__device__ int   g_tgt[B_DIM];
__device__ __align__(16) __nv_bfloat16 g_xhi[(size_t)B_DIM * D_DIM];
__device__ __align__(16) __nv_bfloat16 g_xlo[(size_t)B_DIM * D_DIM];
__device__ __align__(16) __nv_bfloat16 g_whi[(size_t)C_DIM * D_DIM];
__device__ __align__(16) __nv_bfloat16 g_wlo[(size_t)C_DIM * D_DIM];

// ---------------- helpers ----------------------------------------------------
static __device__ __forceinline__ uint32_t smem_u32(const void* p) {
    uint32_t a;
    asm("{ .reg .u64 t; cvta.to.shared.u64 t, %1; cvt.u32.u64 %0, t; }" : "=r"(a) : "l"(p));
    return a;
}
static __device__ __forceinline__ void cp16(uint32_t dst, const void* src) {
    asm volatile("cp.async.cg.shared.global [%0], [%1], 16;" :: "r"(dst), "l"(src) : "memory");
}
static __device__ __forceinline__ void ldsm_x4(uint32_t* r, uint32_t addr) {
    asm volatile("ldmatrix.sync.aligned.m8n8.x4.shared.b16 {%0,%1,%2,%3}, [%4];"
                 : "=r"(r[0]), "=r"(r[1]), "=r"(r[2]), "=r"(r[3]) : "r"(addr));
}
static __device__ __forceinline__ void mma_bf16(float* d, const uint32_t* a,
                                                uint32_t b0, uint32_t b1) {
    asm volatile(
        "mma.sync.aligned.m16n8k16.row.col.f32.bf16.bf16.f32 "
        "{%0,%1,%2,%3}, {%4,%5,%6,%7}, {%8,%9}, {%0,%1,%2,%3};"
        : "+f"(d[0]), "+f"(d[1]), "+f"(d[2]), "+f"(d[3])
        : "r"(a[0]), "r"(a[1]), "r"(a[2]), "r"(a[3]), "r"(b0), "r"(b1));
}

// ---------------- fused rownorm + bf16 hi/lo convert -------------------------
__global__ void prep_kernel(const float* __restrict__ src,
                            float* __restrict__ invn,
                            __nv_bfloat16* __restrict__ hi,
                            __nv_bfloat16* __restrict__ lo) {
    int row = blockIdx.x;
    size_t base = (size_t)row * D_DIM + threadIdx.x * 4;
    float4 v = *reinterpret_cast<const float4*>(src + base);

    float s = v.x * v.x + v.y * v.y + v.z * v.z + v.w * v.w;
    #pragma unroll
    for (int o = 16; o > 0; o >>= 1) s += __shfl_down_sync(0xffffffffu, s, o);
    __shared__ float ws[4];
    int lane = threadIdx.x & 31, w = threadIdx.x >> 5;
    if (lane == 0) ws[w] = s;

    float f[4] = {v.x, v.y, v.z, v.w};
    __nv_bfloat16 h[4], l[4];
    #pragma unroll
    for (int i = 0; i < 4; i++) {
        h[i] = __float2bfloat16_rn(f[i]);
        l[i] = __float2bfloat16_rn(f[i] - __bfloat162float(h[i]));
    }
    *reinterpret_cast<uint2*>(hi + base) =
        make_uint2(*(uint32_t*)&h[0] | ((uint32_t)*(uint16_t*)&h[1] << 16),
                   *(uint32_t*)&h[2] | ((uint32_t)*(uint16_t*)&h[3] << 16));
    *reinterpret_cast<uint2*>(lo + base) =
        make_uint2(*(uint32_t*)&l[0] | ((uint32_t)*(uint16_t*)&l[1] << 16),
                   *(uint32_t*)&l[2] | ((uint32_t)*(uint16_t*)&l[3] << 16));

    __syncthreads();
    if (threadIdx.x == 0)
        invn[row] = 1.0f / fmaxf(sqrtf(ws[0] + ws[1] + ws[2] + ws[3]), 1e-12f);
}

// ---------------- decode targets (proven global probe) ----------------------
__global__ void decode_targets(const void* __restrict__ targets,
                               int* __restrict__ tgt) {
    const int tid = threadIdx.x;  // one block, 1024 threads
    const int* ti = reinterpret_cast<const int*>(targets);
    int odd = ti[2 * tid + 1];
    int any_nonzero = __syncthreads_or(odd != 0);
    const bool is64 = (any_nonzero == 0);
    #pragma unroll
    for (int r = 0; r < 2; r++) {
        int b = tid + r * 1024;
        int t;
        if (is64) t = (int)reinterpret_cast<const long long*>(targets)[b];
        else      t = ti[b];
        tgt[b] = t;
    }
}

// ---------------- GEMM: bf16 mma.sync, 3-product compensated ----------------
// CTA tile 128(m) x 256(n), BK = 64. 512 threads, 16 warps (4m x 4n),
// warp tile m32 x n64. 2-stage cp.async pipeline, 96KB/stage.
// smem: [0..512) invnx, [512..1536) invnw, [1536..2048) targets(int),
//       [2048 + s*98304): stage s = Ahi 16K | Alo 16K | Bhi 32K | Blo 32K
#define STAGE_B 98304u
#define SMEM_TOTAL (2048u + 2u * STAGE_B)

static __device__ __forceinline__ uint32_t swz(uint32_t row, uint32_t quad) {
    return row * 128u + ((quad ^ (row & 7u)) << 4);
}

__global__ void __launch_bounds__(512, 1)
gemm_kernel(float* __restrict__ out_loss, float* __restrict__ out_pred) {
    extern __shared__ __align__(128) unsigned char smem[];
    const uint32_t sb = smem_u32(smem);
    const uint32_t st0 = sb + 2048u;
    const int tid = threadIdx.x;
    const int wid = tid >> 5, lane = tid & 31;
    const int wm = wid & 3, wn = wid >> 2;    // 4m x 4n warp grid

    const int bid = blockIdx.x;          // m-fastest: consecutive CTAs share W panel
    const int mt = bid & 15, nt = bid >> 4;
    const int m0 = mt * 128, n0 = nt * 256;

    float* s_nx = reinterpret_cast<float*>(smem);
    float* s_nw = reinterpret_cast<float*>(smem + 512);
    int*   s_tg = reinterpret_cast<int*>(smem + 1536);
    if (tid < 128) {
        s_nx[tid] = g_invnx[m0 + tid];
        s_tg[tid] = g_tgt[m0 + tid] - n0;   // relative column of margin target
    }
    if (tid < 256) s_nw[tid] = g_invnw[n0 + tid];
    __syncthreads();

    // ---- g2s issue for one K-chunk (64 halves = 128B rows) into stage s ----
    auto issue = [&](int s, int chunk) {
        uint32_t st = st0 + (uint32_t)s * STAGE_B;
        int k0 = chunk * 64;
        #pragma unroll
        for (int i = 0; i < 2; i++) {          // A: 1024 cp16 per buffer
            int idx = tid + i * 512;
            uint32_t row = (uint32_t)idx >> 3, q = (uint32_t)idx & 7;
            uint32_t d = st + swz(row, q);
            size_t goff = ((size_t)(m0 + row) * D_DIM + k0 + q * 8);
            cp16(d,          g_xhi + goff);
            cp16(d + 16384u, g_xlo + goff);
        }
        #pragma unroll
        for (int i = 0; i < 4; i++) {          // B: 2048 cp16 per buffer
            int idx = tid + i * 512;
            uint32_t row = (uint32_t)idx >> 3, q = (uint32_t)idx & 7;
            uint32_t d = st + 32768u + swz(row, q);
            size_t goff = ((size_t)(n0 + row) * D_DIM + k0 + q * 8);
            cp16(d,          g_whi + goff);
            cp16(d + 32768u, g_wlo + goff);
        }
        asm volatile("cp.async.commit_group;" ::: "memory");
    };

    float acc[2][8][4];
    #pragma unroll
    for (int i = 0; i < 2; i++)
        #pragma unroll
        for (int j = 0; j < 8; j++)
            #pragma unroll
            for (int q = 0; q < 4; q++) acc[i][j][q] = 0.0f;

    issue(0, 0);
    issue(1, 1);

    const uint32_t arow = lane & 15;      // ldmatrix row within 16
    const uint32_t akq  = lane >> 4;      // k-quad select (0/1)

    #pragma unroll 1
    for (int c = 0; c < 8; c++) {
        if (c < 6) asm volatile("cp.async.wait_group 1;" ::: "memory");
        else       asm volatile("cp.async.wait_group 0;" ::: "memory");
        __syncthreads();

        uint32_t st = st0 + (uint32_t)(c & 1) * STAGE_B;
        #pragma unroll
        for (int s = 0; s < 4; s++) {     // 4 k16 steps
            uint32_t qb = 2 * s + akq;
            uint32_t ah[2][4], al[2][4];
            #pragma unroll
            for (int mi = 0; mi < 2; mi++) {
                uint32_t row = (uint32_t)(wm * 32 + mi * 16) + arow;
                uint32_t a = st + swz(row, qb);
                ldsm_x4(ah[mi], a);
                ldsm_x4(al[mi], a + 16384u);
            }
            // B in two halves to cap live registers (~96 live total)
            #pragma unroll
            for (int half = 0; half < 2; half++) {
                uint32_t bh[2][4], bl[2][4];
                #pragma unroll
                for (int nj = 0; nj < 2; nj++) {
                    uint32_t row = (uint32_t)(wn * 64 + (half * 2 + nj) * 16) + arow;
                    uint32_t b = st + 32768u + swz(row, qb);
                    ldsm_x4(bh[nj], b);
                    ldsm_x4(bl[nj], b + 32768u);
                }
                #pragma unroll
                for (int mi = 0; mi < 2; mi++)
                    #pragma unroll
                    for (int j = 0; j < 4; j++) {
                        int nb = half * 4 + j;
                        int nj = j >> 1, sel = j & 1;
                        mma_bf16(acc[mi][nb], ah[mi], bh[nj][0 + sel], bh[nj][2 + sel]);
                        mma_bf16(acc[mi][nb], ah[mi], bl[nj][0 + sel], bl[nj][2 + sel]);
                        mma_bf16(acc[mi][nb], al[mi], bh[nj][0 + sel], bh[nj][2 + sel]);
                    }
            }
        }
        __syncthreads();
        if (c + 2 < 8) issue(c & 1, c + 2);
    }

    // ---- epilogue: fold invnx*invnw*SCALE; margin fused into loss stores ----
    const int gr = lane >> 2, gc = lane & 3;
    #pragma unroll
    for (int mi = 0; mi < 2; mi++) {
        int rl = wm * 32 + mi * 16 + gr;      // local row (and rl+8)
        float sx0 = s_nx[rl] * SCALE_F;
        float sx1 = s_nx[rl + 8] * SCALE_F;
        int t0 = s_tg[rl];                    // margin col relative to n0
        int t1 = s_tg[rl + 8];
        size_t off0 = (size_t)(m0 + rl) * C_DIM + n0;
        size_t off1 = off0 + (size_t)8 * C_DIM;
        #pragma unroll
        for (int nb = 0; nb < 8; nb++) {
            int col = wn * 64 + nb * 8 + gc * 2;
            float sw0 = s_nw[col], sw1 = s_nw[col + 1];
            float2 v0 = make_float2(acc[mi][nb][0] * sx0 * sw0,
                                    acc[mi][nb][1] * sx0 * sw1);
            float2 v1 = make_float2(acc[mi][nb][2] * sx1 * sw0,
                                    acc[mi][nb][3] * sx1 * sw1);
            *reinterpret_cast<float2*>(out_pred + off0 + col) = v0;
            *reinterpret_cast<float2*>(out_pred + off1 + col) = v1;
            float2 u0 = v0, u1 = v1;
            if (t0 == col)     u0.x -= MARGIN_F;
            if (t0 == col + 1) u0.y -= MARGIN_F;
            if (t1 == col)     u1.x -= MARGIN_F;
            if (t1 == col + 1) u1.y -= MARGIN_F;
            *reinterpret_cast<float2*>(out_loss + off0 + col) = u0;
            *reinterpret_cast<float2*>(out_loss + off1 + col) = u1;
        }
    }
}

// ---------------------------------------------------------------------------
extern "C" void kernel_launch(void* const* d_in, const int* in_sizes, int n_in,
                              void* d_out, int out_size) {
    const float* x  = (const float*)d_in[0];
    const float* w  = (const float*)d_in[1];
    const void*  tg = d_in[2];

    float* out_loss = (float*)d_out;
    float* out_pred = out_loss + (size_t)B_DIM * C_DIM;

    float *invnx, *invnw;
    int* tgt;
    __nv_bfloat16 *xhi, *xlo, *whi, *wlo;
    cudaGetSymbolAddress((void**)&invnx, g_invnx);
    cudaGetSymbolAddress((void**)&invnw, g_invnw);
    cudaGetSymbolAddress((void**)&tgt,   g_tgt);
    cudaGetSymbolAddress((void**)&xhi, g_xhi);
    cudaGetSymbolAddress((void**)&xlo, g_xlo);
    cudaGetSymbolAddress((void**)&whi, g_whi);
    cudaGetSymbolAddress((void**)&wlo, g_wlo);

    decode_targets<<<1, 1024>>>(tg, tgt);
    prep_kernel<<<B_DIM, 128>>>(x, invnx, xhi, xlo);
    prep_kernel<<<C_DIM, 128>>>(w, invnw, whi, wlo);

    cudaFuncSetAttribute(gemm_kernel, cudaFuncAttributeMaxDynamicSharedMemorySize, SMEM_TOTAL);
    gemm_kernel<<<2000, 512, SMEM_TOTAL>>>(out_loss, out_pred);
}